// round 2
// baseline (speedup 1.0000x reference)
#include <cuda_runtime.h>

#define N_SRC   50000
#define N_DST   50000
#define N_EDGES 800000
#define D       128     // D_IN = D_HID = D_OUT

// Scratch (device globals — allocation-free per harness rules).
// __align__(16) is load-bearing: float4 loads + red.global.add.v4.f32.
__device__ __align__(16) float g_nsrc[N_SRC * D];   // relu(h_src @ Q_w^T + Q_b)
__device__ __align__(16) float g_nacc[N_DST * D];   // segment-summed messages
__device__ float g_ws[N_DST];                        // segment-summed weights

// ---------------------------------------------------------------------------
// Zero the accumulators (float4 stores, grid-stride)
// ---------------------------------------------------------------------------
__global__ void zero_kernel() {
    const int n4 = (N_DST * D) / 4;
    float4* p = reinterpret_cast<float4*>(g_nacc);
    const float4 z = make_float4(0.f, 0.f, 0.f, 0.f);
    for (int i = blockIdx.x * blockDim.x + threadIdx.x; i < n4;
         i += gridDim.x * blockDim.x)
        p[i] = z;
    for (int i = blockIdx.x * blockDim.x + threadIdx.x; i < N_DST;
         i += gridDim.x * blockDim.x)
        g_ws[i] = 0.f;
}

// ---------------------------------------------------------------------------
// Tiled fp32 GEMM:  OUT[i][j] = relu( sum_k A[i][k] * W[j][k] + bias[j] )
//   MODE 0: A = h_src (KDIM=128), OUT = g_nsrc
//   MODE 1: A[i][k] = (k<128 ? g_nacc[i][k] * 1/max(ws[i],1) : h_dst[i][k-128]),
//           KDIM=256, OUT = out param (d_out)
// Block tile 64 rows x 128 cols, BK=16, 256 threads, 4x8 per-thread tile.
// ---------------------------------------------------------------------------
template <int KDIM, int MODE>
__global__ void gemm_kernel(const float* __restrict__ A0,
                            const float* __restrict__ W,
                            const float* __restrict__ bias,
                            float* __restrict__ out,
                            int nrows)
{
    __shared__ float As[16][65];    // [k][row]
    __shared__ float Bs[16][129];   // [k][col]
    __shared__ float invWs[64];

    const int i0  = blockIdx.x * 64;
    const int tid = threadIdx.x;
    const int tx  = tid & 15;       // col group
    const int ty  = tid >> 4;       // row group

    if (MODE == 1) {
        if (tid < 64) {
            int r = i0 + tid;
            float w = (r < nrows) ? g_ws[r] : 1.f;
            invWs[tid] = 1.0f / fmaxf(w, 1.0f);
        }
        __syncthreads();
    }

    float acc[4][8];
#pragma unroll
    for (int r = 0; r < 4; ++r)
#pragma unroll
        for (int c = 0; c < 8; ++c) acc[r][c] = 0.f;

    for (int kc = 0; kc < KDIM; kc += 16) {
        // A tile: 64 rows x 16 k  (1024 elems, 4 per thread)
#pragma unroll
        for (int it = 0; it < 4; ++it) {
            int e   = it * 256 + tid;
            int k   = e & 15;
            int row = e >> 4;
            int gi  = i0 + row;
            float v = 0.f;
            if (gi < nrows) {
                int gk = kc + k;
                if (MODE == 0) {
                    v = A0[gi * KDIM + gk];
                } else {
                    if (gk < 128) v = g_nacc[gi * 128 + gk] * invWs[row];
                    else          v = A0[gi * 128 + (gk - 128)];
                }
            }
            As[k][row] = v;
        }
        // B tile: 128 cols x 16 k  (2048 elems, 8 per thread)
#pragma unroll
        for (int it = 0; it < 8; ++it) {
            int e = it * 256 + tid;
            int k = e & 15;
            int j = e >> 4;
            Bs[k][j] = W[j * KDIM + kc + k];
        }
        __syncthreads();

#pragma unroll
        for (int kk = 0; kk < 16; ++kk) {
            float a[4], b[8];
#pragma unroll
            for (int r = 0; r < 4; ++r) a[r] = As[kk][ty + 16 * r];
#pragma unroll
            for (int c = 0; c < 8; ++c) b[c] = Bs[kk][tx + 16 * c];
#pragma unroll
            for (int r = 0; r < 4; ++r)
#pragma unroll
                for (int c = 0; c < 8; ++c)
                    acc[r][c] = fmaf(a[r], b[c], acc[r][c]);
        }
        __syncthreads();
    }

    // Epilogue: bias + relu
    float* op = (MODE == 0) ? g_nsrc : out;
#pragma unroll
    for (int c = 0; c < 8; ++c) {
        float bb = bias[tx + 16 * c];
#pragma unroll
        for (int r = 0; r < 4; ++r) {
            int gi = i0 + ty + 16 * r;
            if (gi < nrows) {
                float v = acc[r][c] + bb;
                op[gi * D + tx + 16 * c] = fmaxf(v, 0.f);
            }
        }
    }
}

// ---------------------------------------------------------------------------
// Edge aggregation: one warp per edge.
//   g_nacc[dst] += n_src[src] * w   (vectorized red.global.add.v4.f32)
//   g_ws[dst]   += w
// n_src (25.6 MB) and g_nacc (25.6 MB) are L2-resident.
// Indices are int32 (JAX x64-disabled downcasts the declared int64).
// ---------------------------------------------------------------------------
__global__ void aggregate_kernel(const float* __restrict__ weights,
                                 const int* __restrict__ esrc,
                                 const int* __restrict__ edst)
{
    const int gwarp = (blockIdx.x * blockDim.x + threadIdx.x) >> 5;
    const int lane  = threadIdx.x & 31;
    if (gwarp >= N_EDGES) return;

    const int   s = esrc[gwarp];
    const int   d = edst[gwarp];
    const float w = weights[gwarp];

    const float4* src = reinterpret_cast<const float4*>(g_nsrc + (size_t)s * D);
    float4 v = src[lane];
    v.x *= w; v.y *= w; v.z *= w; v.w *= w;

    float* dst = g_nacc + (size_t)d * D + lane * 4;
    asm volatile("red.global.add.v4.f32 [%0], {%1,%2,%3,%4};"
                 :: "l"(dst), "f"(v.x), "f"(v.y), "f"(v.z), "f"(v.w)
                 : "memory");

    if (lane == 0)
        atomicAdd(&g_ws[d], w);
}

// ---------------------------------------------------------------------------
extern "C" void kernel_launch(void* const* d_in, const int* in_sizes, int n_in,
                              void* d_out, int out_size)
{
    const float* h_src   = (const float*)d_in[0];
    const float* h_dst   = (const float*)d_in[1];
    const float* weights = (const float*)d_in[2];
    const int*   esrc    = (const int*)d_in[3];
    const int*   edst    = (const int*)d_in[4];
    const float* Q_w     = (const float*)d_in[5];
    const float* Q_b     = (const float*)d_in[6];
    const float* W_w     = (const float*)d_in[7];
    const float* W_b     = (const float*)d_in[8];
    float*       out     = (float*)d_out;

    zero_kernel<<<2048, 256>>>();

    gemm_kernel<128, 0><<<(N_SRC + 63) / 64, 256>>>(h_src, Q_w, Q_b, nullptr, N_SRC);

    aggregate_kernel<<<N_EDGES / 8, 256>>>(weights, esrc, edst);

    gemm_kernel<256, 1><<<(N_DST + 63) / 64, 256>>>(h_dst, W_w, W_b, out, N_DST);
}

// round 3
// speedup vs baseline: 1.2515x; 1.2515x over previous
#include <cuda_runtime.h>

#define N_SRC   50000
#define N_DST   50000
#define N_EDGES 800000
#define D       128     // D_IN = D_HID = D_OUT

// Scratch (device globals — allocation-free per harness rules).
__device__ __align__(16) float g_nsrc[N_SRC * D];   // relu(h_src @ Q_w^T + Q_b)
__device__ __align__(16) float g_nacc[N_DST * D];   // segment-summed messages
__device__ float g_ws[N_DST];                        // segment-summed weights

// ---------------------------------------------------------------------------
// Zero the accumulators (float4 stores, grid-stride)
// ---------------------------------------------------------------------------
__global__ void zero_kernel() {
    const int n4 = (N_DST * D) / 4;
    float4* p = reinterpret_cast<float4*>(g_nacc);
    const float4 z = make_float4(0.f, 0.f, 0.f, 0.f);
    for (int i = blockIdx.x * blockDim.x + threadIdx.x; i < n4;
         i += gridDim.x * blockDim.x)
        p[i] = z;
    for (int i = blockIdx.x * blockDim.x + threadIdx.x; i < N_DST;
         i += gridDim.x * blockDim.x)
        g_ws[i] = 0.f;
}

// ---------------------------------------------------------------------------
// SGEMM:  OUT[i][j] = relu( sum_k A[i][k] * W[j][k] + bias[j] ),  j < 128
//   MODE 0: A = h_src (KDIM=128), OUT = g_nsrc
//   MODE 1: A[i][k] = (k<128 ? g_nacc[i][k]/max(ws[i],1) : h_dst[i][k-128]),
//           KDIM=256, OUT = out param (d_out)
// 128x128 block tile, BK=8, 256 threads, 8x8 per-thread micro-tile,
// float4 SMEM fragments (4 LDS.128 per 64 FFMA).
// ---------------------------------------------------------------------------
template <int KDIM, int MODE>
__global__ void __launch_bounds__(256, 2)
gemm_kernel(const float* __restrict__ A0,
            const float* __restrict__ W,
            const float* __restrict__ bias,
            float* __restrict__ out,
            int nrows)
{
    __shared__ float As[8][132];   // [k][row], pad keeps 16B alignment per row
    __shared__ float Bs[8][132];   // [k][col]
    __shared__ float invWs[128];

    const int i0  = blockIdx.x * 128;
    const int tid = threadIdx.x;

    if (MODE == 1) {
        if (tid < 128) {
            int r = i0 + tid;
            float w = (r < nrows) ? g_ws[r] : 1.f;
            invWs[tid] = 1.0f / fmaxf(w, 1.0f);
        }
        __syncthreads();
    }

    // Loader mapping: each thread loads one float4 of A and one of B per iter.
    const int lrow = tid >> 1;          // 0..127 (row of A / col of B=W)
    const int lkg  = (tid & 1) * 4;     // k offset 0 or 4

    // Compute mapping: 16x16 thread grid, 8x8 micro-tile each.
    const int tx = tid & 15;
    const int ty = tid >> 4;

    float acc[8][8];
#pragma unroll
    for (int r = 0; r < 8; ++r)
#pragma unroll
        for (int c = 0; c < 8; ++c) acc[r][c] = 0.f;

    const int gi = i0 + lrow;
    const bool arow_ok = (gi < nrows);
    const float ascale = (MODE == 1 && arow_ok) ? invWs[lrow] : 1.0f;

    for (int kc = 0; kc < KDIM; kc += 8) {
        // ---- A tile: 128 rows x 8 k ----
        float4 av = make_float4(0.f, 0.f, 0.f, 0.f);
        if (arow_ok) {
            int gk = kc + lkg;
            if (MODE == 0) {
                av = *(const float4*)(A0 + (size_t)gi * KDIM + gk);
            } else if (gk < 128) {
                av = *(const float4*)(g_nacc + (size_t)gi * 128 + gk);
                av.x *= ascale; av.y *= ascale; av.z *= ascale; av.w *= ascale;
            } else {
                av = *(const float4*)(A0 + (size_t)gi * 128 + (gk - 128));
            }
        }
        As[lkg + 0][lrow] = av.x;
        As[lkg + 1][lrow] = av.y;
        As[lkg + 2][lrow] = av.z;
        As[lkg + 3][lrow] = av.w;

        // ---- B tile: 128 cols x 8 k  (Bs[k][j] = W[j][k]) ----
        float4 bv = *(const float4*)(W + (size_t)lrow * KDIM + kc + lkg);
        Bs[lkg + 0][lrow] = bv.x;
        Bs[lkg + 1][lrow] = bv.y;
        Bs[lkg + 2][lrow] = bv.z;
        Bs[lkg + 3][lrow] = bv.w;

        __syncthreads();

#pragma unroll
        for (int kk = 0; kk < 8; ++kk) {
            float a[8], b[8];
            *(float4*)(a)     = *(const float4*)&As[kk][ty * 4];
            *(float4*)(a + 4) = *(const float4*)&As[kk][64 + ty * 4];
            *(float4*)(b)     = *(const float4*)&Bs[kk][tx * 4];
            *(float4*)(b + 4) = *(const float4*)&Bs[kk][64 + tx * 4];
#pragma unroll
            for (int r = 0; r < 8; ++r)
#pragma unroll
                for (int c = 0; c < 8; ++c)
                    acc[r][c] = fmaf(a[r], b[c], acc[r][c]);
        }
        __syncthreads();
    }

    // ---- Epilogue: bias + relu, float4 stores ----
    float* op = (MODE == 0) ? g_nsrc : out;
    float bb[8];
#pragma unroll
    for (int ch = 0; ch < 2; ++ch) {
        *(float4*)(bb + ch * 4) = *(const float4*)(bias + ch * 64 + tx * 4);
    }
#pragma unroll
    for (int rh = 0; rh < 2; ++rh) {
#pragma unroll
        for (int r = 0; r < 4; ++r) {
            int row = i0 + rh * 64 + ty * 4 + r;
            if (row < nrows) {
#pragma unroll
                for (int ch = 0; ch < 2; ++ch) {
                    float4 v;
                    v.x = fmaxf(acc[rh * 4 + r][ch * 4 + 0] + bb[ch * 4 + 0], 0.f);
                    v.y = fmaxf(acc[rh * 4 + r][ch * 4 + 1] + bb[ch * 4 + 1], 0.f);
                    v.z = fmaxf(acc[rh * 4 + r][ch * 4 + 2] + bb[ch * 4 + 2], 0.f);
                    v.w = fmaxf(acc[rh * 4 + r][ch * 4 + 3] + bb[ch * 4 + 3], 0.f);
                    *(float4*)(op + (size_t)row * D + ch * 64 + tx * 4) = v;
                }
            }
        }
    }
}

// ---------------------------------------------------------------------------
// Edge aggregation: one warp per edge.
//   g_nacc[dst] += n_src[src] * w   (vectorized red.global.add.v4.f32)
//   g_ws[dst]   += w
// ---------------------------------------------------------------------------
__global__ void aggregate_kernel(const float* __restrict__ weights,
                                 const int* __restrict__ esrc,
                                 const int* __restrict__ edst)
{
    const int gwarp = (blockIdx.x * blockDim.x + threadIdx.x) >> 5;
    const int lane  = threadIdx.x & 31;
    if (gwarp >= N_EDGES) return;

    const int   s = esrc[gwarp];
    const int   d = edst[gwarp];
    const float w = weights[gwarp];

    const float4* src = reinterpret_cast<const float4*>(g_nsrc + (size_t)s * D);
    float4 v = src[lane];
    v.x *= w; v.y *= w; v.z *= w; v.w *= w;

    float* dst = g_nacc + (size_t)d * D + lane * 4;
    asm volatile("red.global.add.v4.f32 [%0], {%1,%2,%3,%4};"
                 :: "l"(dst), "f"(v.x), "f"(v.y), "f"(v.z), "f"(v.w)
                 : "memory");

    if (lane == 0)
        atomicAdd(&g_ws[d], w);
}

// ---------------------------------------------------------------------------
extern "C" void kernel_launch(void* const* d_in, const int* in_sizes, int n_in,
                              void* d_out, int out_size)
{
    const float* h_src   = (const float*)d_in[0];
    const float* h_dst   = (const float*)d_in[1];
    const float* weights = (const float*)d_in[2];
    const int*   esrc    = (const int*)d_in[3];
    const int*   edst    = (const int*)d_in[4];
    const float* Q_w     = (const float*)d_in[5];
    const float* Q_b     = (const float*)d_in[6];
    const float* W_w     = (const float*)d_in[7];
    const float* W_b     = (const float*)d_in[8];
    float*       out     = (float*)d_out;

    zero_kernel<<<2048, 256>>>();

    gemm_kernel<128, 0><<<(N_SRC + 127) / 128, 256>>>(h_src, Q_w, Q_b, nullptr, N_SRC);

    aggregate_kernel<<<N_EDGES / 8, 256>>>(weights, esrc, edst);

    gemm_kernel<256, 1><<<(N_DST + 127) / 128, 256>>>(h_dst, W_w, W_b, out, N_DST);
}

// round 4
// speedup vs baseline: 1.3219x; 1.0563x over previous
#include <cuda_runtime.h>
#include <cstdint>

#define N_SRC   50000
#define N_DST   50000
#define N_EDGES 800000
#define D       128

// Scratch (device globals — allocation-free per harness rules).
__device__ __align__(16) float g_nsrc[N_SRC * D];
__device__ __align__(16) float g_nacc[N_DST * D];
__device__ float g_ws[N_DST];

// ---------------------------------------------------------------------------
__global__ void zero_kernel() {
    const int n4 = (N_DST * D) / 4;
    float4* p = reinterpret_cast<float4*>(g_nacc);
    const float4 z = make_float4(0.f, 0.f, 0.f, 0.f);
    for (int i = blockIdx.x * blockDim.x + threadIdx.x; i < n4;
         i += gridDim.x * blockDim.x)
        p[i] = z;
    for (int i = blockIdx.x * blockDim.x + threadIdx.x; i < N_DST;
         i += gridDim.x * blockDim.x)
        g_ws[i] = 0.f;
}

// ---------------------------------------------------------------------------
// tf32x3 helpers
// ---------------------------------------------------------------------------
__device__ __forceinline__ uint32_t f2tf(float x) {
    uint32_t r;
    asm("cvt.rna.tf32.f32 %0, %1;" : "=r"(r) : "f"(x));
    return r;
}

__device__ __forceinline__ void mma_tf32(float* d, const uint32_t* a,
                                         const uint32_t* b) {
    asm volatile(
        "mma.sync.aligned.m16n8k8.row.col.f32.tf32.tf32.f32 "
        "{%0,%1,%2,%3}, {%4,%5,%6,%7}, {%8,%9}, {%0,%1,%2,%3};"
        : "+f"(d[0]), "+f"(d[1]), "+f"(d[2]), "+f"(d[3])
        : "r"(a[0]), "r"(a[1]), "r"(a[2]), "r"(a[3]),
          "r"(b[0]), "r"(b[1]));
}

// ---------------------------------------------------------------------------
// Tensor-core GEMM (tf32x3, fp32-class accuracy):
//   OUT[i][j] = relu( sum_k A[i][k] * W[j][k] + bias[j] ),  j < 128
//   MODE 0: A = h_src (KDIM=128), OUT = g_nsrc
//   MODE 1: A[i][k] = (k<128 ? g_nacc[i][k]/max(ws[i],1) : h_dst[i][k-128]),
//           KDIM=256, OUT = d_out
// Block: 128x128 tile, BK=32, 256 threads = 8 warps (4 m-warps x 2 n-warps),
// warp tile 32x64 = 2 m16 tiles x 8 n8 tiles. SMEM pitch 36 -> conflict-free
// fragment loads (bank = 4*(lane>>2) + (lane&3), all distinct).
// ---------------------------------------------------------------------------
template <int KDIM, int MODE>
__global__ void __launch_bounds__(256, 2)
gemm_tf32(const float* __restrict__ A0,
          const float* __restrict__ W,
          const float* __restrict__ bias,
          float* __restrict__ out,
          int nrows)
{
    constexpr int PITCH = 36;
    __shared__ float As[128 * PITCH];
    __shared__ float Bs[128 * PITCH];
    __shared__ float invWs[128];

    const int tid    = threadIdx.x;
    const int i0     = blockIdx.x * 128;
    const int lane   = tid & 31;
    const int wid    = tid >> 5;
    const int warp_m = wid & 3;   // 0..3
    const int warp_n = wid >> 2;  // 0..1
    const int qr     = lane >> 2; // 0..7
    const int qc     = lane & 3;  // 0..3

    if (MODE == 1) {
        if (tid < 128) {
            int r = i0 + tid;
            float w = (r < nrows) ? g_ws[r] : 1.f;
            invWs[tid] = 1.0f / fmaxf(w, 1.0f);
        }
    }

    float acc[2][8][4];
#pragma unroll
    for (int mt = 0; mt < 2; ++mt)
#pragma unroll
        for (int nt = 0; nt < 8; ++nt)
#pragma unroll
            for (int r = 0; r < 4; ++r) acc[mt][nt][r] = 0.f;

    const int lrow = tid >> 3;         // 0..31
    const int lkg  = (tid & 7) * 4;    // 0,4,...,28

    for (int kc = 0; kc < KDIM; kc += 32) {
        __syncthreads();   // prev-stage reads done (also orders invWs fill)

#pragma unroll
        for (int it = 0; it < 4; ++it) {
            int row = lrow + 32 * it;       // 0..127
            int gi  = i0 + row;
            int gk  = kc + lkg;
            // A tile
            float4 av = make_float4(0.f, 0.f, 0.f, 0.f);
            if (gi < nrows) {
                if (MODE == 0) {
                    av = *(const float4*)(A0 + (size_t)gi * 128 + gk);
                } else if (gk < 128) {
                    av = *(const float4*)(g_nacc + (size_t)gi * 128 + gk);
                    float s = invWs[row];
                    av.x *= s; av.y *= s; av.z *= s; av.w *= s;
                } else {
                    av = *(const float4*)(A0 + (size_t)gi * 128 + (gk - 128));
                }
            }
            *(float4*)(As + row * PITCH + lkg) = av;
            // B tile (W is [128][KDIM], j = row always valid)
            float4 bv = *(const float4*)(W + (size_t)row * KDIM + gk);
            *(float4*)(Bs + row * PITCH + lkg) = bv;
        }
        __syncthreads();

#pragma unroll
        for (int s = 0; s < 4; ++s) {
            const int ks = s * 8;
            // A fragments (hi/lo)
            uint32_t ahi[2][4], alo[2][4];
#pragma unroll
            for (int mt = 0; mt < 2; ++mt) {
                const int rb = warp_m * 32 + mt * 16;
                float v[4];
                v[0] = As[(rb + qr)     * PITCH + ks + qc];
                v[1] = As[(rb + qr + 8) * PITCH + ks + qc];
                v[2] = As[(rb + qr)     * PITCH + ks + qc + 4];
                v[3] = As[(rb + qr + 8) * PITCH + ks + qc + 4];
#pragma unroll
                for (int r = 0; r < 4; ++r) {
                    ahi[mt][r] = f2tf(v[r]);
                    alo[mt][r] = f2tf(v[r] - __uint_as_float(ahi[mt][r]));
                }
            }
#pragma unroll
            for (int nt = 0; nt < 8; ++nt) {
                const int nb = warp_n * 64 + nt * 8;
                float w0 = Bs[(nb + qr) * PITCH + ks + qc];
                float w1 = Bs[(nb + qr) * PITCH + ks + qc + 4];
                uint32_t bhi[2], blo[2];
                bhi[0] = f2tf(w0); blo[0] = f2tf(w0 - __uint_as_float(bhi[0]));
                bhi[1] = f2tf(w1); blo[1] = f2tf(w1 - __uint_as_float(bhi[1]));
#pragma unroll
                for (int mt = 0; mt < 2; ++mt) {
                    mma_tf32(acc[mt][nt], ahi[mt], bhi);
                    mma_tf32(acc[mt][nt], alo[mt], bhi);
                    mma_tf32(acc[mt][nt], ahi[mt], blo);
                }
            }
        }
    }

    // ---- Epilogue: bias + relu, float2 stores ----
    float* op = (MODE == 0) ? g_nsrc : out;
#pragma unroll
    for (int mt = 0; mt < 2; ++mt) {
#pragma unroll
        for (int half = 0; half < 2; ++half) {
            const int row = i0 + warp_m * 32 + mt * 16 + qr + half * 8;
            if (row < nrows) {
#pragma unroll
                for (int nt = 0; nt < 8; ++nt) {
                    const int col = warp_n * 64 + nt * 8 + qc * 2;
                    float2 v;
                    v.x = fmaxf(acc[mt][nt][half * 2 + 0] + bias[col],     0.f);
                    v.y = fmaxf(acc[mt][nt][half * 2 + 1] + bias[col + 1], 0.f);
                    *(float2*)(op + (size_t)row * 128 + col) = v;
                }
            }
        }
    }
}

// ---------------------------------------------------------------------------
// Edge aggregation: one warp per edge (near its L2/LTS roofline).
// ---------------------------------------------------------------------------
__global__ void aggregate_kernel(const float* __restrict__ weights,
                                 const int* __restrict__ esrc,
                                 const int* __restrict__ edst)
{
    const int gwarp = (blockIdx.x * blockDim.x + threadIdx.x) >> 5;
    const int lane  = threadIdx.x & 31;
    if (gwarp >= N_EDGES) return;

    const int   s = esrc[gwarp];
    const int   d = edst[gwarp];
    const float w = weights[gwarp];

    const float4* src = reinterpret_cast<const float4*>(g_nsrc + (size_t)s * D);
    float4 v = src[lane];
    v.x *= w; v.y *= w; v.z *= w; v.w *= w;

    float* dst = g_nacc + (size_t)d * D + lane * 4;
    asm volatile("red.global.add.v4.f32 [%0], {%1,%2,%3,%4};"
                 :: "l"(dst), "f"(v.x), "f"(v.y), "f"(v.z), "f"(v.w)
                 : "memory");

    if (lane == 0)
        atomicAdd(&g_ws[d], w);
}

// ---------------------------------------------------------------------------
extern "C" void kernel_launch(void* const* d_in, const int* in_sizes, int n_in,
                              void* d_out, int out_size)
{
    const float* h_src   = (const float*)d_in[0];
    const float* h_dst   = (const float*)d_in[1];
    const float* weights = (const float*)d_in[2];
    const int*   esrc    = (const int*)d_in[3];
    const int*   edst    = (const int*)d_in[4];
    const float* Q_w     = (const float*)d_in[5];
    const float* Q_b     = (const float*)d_in[6];
    const float* W_w     = (const float*)d_in[7];
    const float* W_b     = (const float*)d_in[8];
    float*       out     = (float*)d_out;

    zero_kernel<<<2048, 256>>>();

    gemm_tf32<128, 0><<<(N_SRC + 127) / 128, 256>>>(h_src, Q_w, Q_b, nullptr, N_SRC);

    aggregate_kernel<<<N_EDGES / 8, 256>>>(weights, esrc, edst);

    gemm_tf32<256, 1><<<(N_DST + 127) / 128, 256>>>(h_dst, W_w, W_b, out, N_DST);
}

// round 5
// speedup vs baseline: 2.0906x; 1.5815x over previous
#include <cuda_runtime.h>
#include <cuda_bf16.h>
#include <cstdint>

#define N_SRC   50000
#define N_DST   50000
#define N_EDGES 800000
#define D       128
#define SCAN_B  1024
#define NSCAN   ((N_DST + SCAN_B - 1) / SCAN_B)   // 49

// ---------------- device-global scratch (allocation-free) ----------------
__device__ __align__(16) float g_nsrc[N_SRC * D];   // relu(h_src @ Q^T + b)
__device__ __align__(16) float g_nacc[N_DST * D];   // normalized aggregate
__device__ int   g_cnt[NSCAN * SCAN_B];             // per-dst degree (padded)
__device__ int   g_startv[N_DST];                   // CSR start offsets
__device__ int   g_cursor[N_DST];                   // scatter cursors
__device__ int   g_bsum[NSCAN];
__device__ int   g_boff[NSCAN];
__device__ int   g_srcs[N_EDGES];                   // edge src sorted by dst
__device__ float g_wsort[N_EDGES];                  // edge weight sorted by dst

// ---------------------------------------------------------------------------
// CSR build: zero -> histogram -> scan(3) -> scatter
// ---------------------------------------------------------------------------
__global__ void zero_cnt_kernel() {
    int i = blockIdx.x * blockDim.x + threadIdx.x;
    if (i < NSCAN * SCAN_B) g_cnt[i] = 0;
}

__global__ void hist_kernel(const int* __restrict__ edst) {
    int e = blockIdx.x * blockDim.x + threadIdx.x;
    if (e < N_EDGES) atomicAdd(&g_cnt[edst[e]], 1);
}

__global__ void scan_block_kernel() {        // grid = NSCAN, 256 threads
    int b = blockIdx.x;
    int sum = 0;
    for (int j = threadIdx.x; j < SCAN_B; j += 256)
        sum += g_cnt[b * SCAN_B + j];
#pragma unroll
    for (int o = 16; o; o >>= 1) sum += __shfl_down_sync(0xffffffffu, sum, o);
    __shared__ int sw[8];
    if ((threadIdx.x & 31) == 0) sw[threadIdx.x >> 5] = sum;
    __syncthreads();
    if (threadIdx.x < 8) {
        int v = sw[threadIdx.x];
#pragma unroll
        for (int o = 4; o; o >>= 1) v += __shfl_down_sync(0xffu, v, o);
        if (threadIdx.x == 0) g_bsum[b] = v;
    }
}

__global__ void scan_top_kernel() {          // 1 block, 32 threads
    if (threadIdx.x == 0) {
        int run = 0;
        for (int b = 0; b < NSCAN; ++b) { g_boff[b] = run; run += g_bsum[b]; }
    }
}

__global__ void scan_down_kernel() {         // grid = NSCAN, 1024 threads
    __shared__ int sm[SCAN_B];
    int b = blockIdx.x, t = threadIdx.x;
    int i = b * SCAN_B + t;
    int x = g_cnt[i];
    sm[t] = x;
    __syncthreads();
#pragma unroll
    for (int off = 1; off < SCAN_B; off <<= 1) {
        int v = (t >= off) ? sm[t - off] : 0;
        __syncthreads();
        if (t >= off) sm[t] += v;
        __syncthreads();
    }
    int excl = sm[t] - x + g_boff[b];
    if (i < N_DST) { g_startv[i] = excl; g_cursor[i] = excl; }
}

__global__ void scatter_kernel(const int* __restrict__ esrc,
                               const int* __restrict__ edst,
                               const float* __restrict__ weights) {
    int e = blockIdx.x * blockDim.x + threadIdx.x;
    if (e >= N_EDGES) return;
    int d   = edst[e];
    int pos = atomicAdd(&g_cursor[d], 1);
    g_srcs[pos]  = esrc[e];
    g_wsort[pos] = weights[e];
}

// ---------------------------------------------------------------------------
// Aggregation: one warp per destination, register accumulation, single write.
// Writes n/max(ws,1) directly (normalization folded in).
// ---------------------------------------------------------------------------
__global__ void aggregate_csr_kernel() {
    const int warp = (blockIdx.x * blockDim.x + threadIdx.x) >> 5;
    const int lane = threadIdx.x & 31;
    if (warp >= N_DST) return;

    const int beg = g_startv[warp];
    const int n   = g_cnt[warp];

    float4 acc = make_float4(0.f, 0.f, 0.f, 0.f);
    float  wsum = 0.f;

    int   s = 0; float w = 0.f;
    if (n > 0) { s = g_srcs[beg]; w = g_wsort[beg]; }
    for (int i = 0; i < n; ++i) {
        int s2 = 0; float w2 = 0.f;
        if (i + 1 < n) { s2 = g_srcs[beg + i + 1]; w2 = g_wsort[beg + i + 1]; }
        float4 v = *(const float4*)(g_nsrc + (size_t)s * D + lane * 4);
        acc.x = fmaf(v.x, w, acc.x);
        acc.y = fmaf(v.y, w, acc.y);
        acc.z = fmaf(v.z, w, acc.z);
        acc.w = fmaf(v.w, w, acc.w);
        wsum += w;
        s = s2; w = w2;
    }
    const float inv = 1.0f / fmaxf(wsum, 1.0f);
    float4 o = make_float4(acc.x * inv, acc.y * inv, acc.z * inv, acc.w * inv);
    *(float4*)(g_nacc + (size_t)warp * D + lane * 4) = o;
}

// ---------------------------------------------------------------------------
// bf16x3 split helpers
// ---------------------------------------------------------------------------
__device__ __forceinline__ void pack2(float x, float y,
                                      uint32_t& hi, uint32_t& lo) {
    __nv_bfloat162 h = __floats2bfloat162_rn(x, y);
    uint32_t hu = reinterpret_cast<uint32_t&>(h);
    float fx = __uint_as_float(hu << 16);
    float fy = __uint_as_float(hu & 0xFFFF0000u);
    __nv_bfloat162 l = __floats2bfloat162_rn(x - fx, y - fy);
    hi = hu;
    lo = reinterpret_cast<uint32_t&>(l);
}

__device__ __forceinline__ void mma_bf16(float* d, const uint32_t* a,
                                         const uint32_t* b) {
    asm volatile(
        "mma.sync.aligned.m16n8k16.row.col.f32.bf16.bf16.f32 "
        "{%0,%1,%2,%3}, {%4,%5,%6,%7}, {%8,%9}, {%0,%1,%2,%3};"
        : "+f"(d[0]), "+f"(d[1]), "+f"(d[2]), "+f"(d[3])
        : "r"(a[0]), "r"(a[1]), "r"(a[2]), "r"(a[3]),
          "r"(b[0]), "r"(b[1]));
}

// ---------------------------------------------------------------------------
// Tensor-core GEMM (bf16x3, fp32-class accuracy):
//   OUT[i][j] = relu( sum_k A[i][k] * W[j][k] + bias[j] ),  j < 128
//   MODE 0: A = h_src (KDIM=128), OUT = g_nsrc
//   MODE 1: A[i][k] = (k<128 ? g_nacc[i][k] : h_dst[i][k-128]), KDIM=256.
// Block 128x128, BK=32, 8 warps (4m x 2n), warp tile 32x64.
// SMEM: packed bf16x2 hi/lo tiles, pitch 20 u32 -> conflict-free frag loads.
// ---------------------------------------------------------------------------
template <int KDIM, int MODE>
__global__ void __launch_bounds__(256, 2)
gemm_bf16x3(const float* __restrict__ A0,
            const float* __restrict__ W,
            const float* __restrict__ bias,
            float* __restrict__ out,
            int nrows)
{
    constexpr int P = 20;                 // u32 pitch per row (16 data + 4 pad)
    __shared__ uint32_t As_hi[128 * P];
    __shared__ uint32_t As_lo[128 * P];
    __shared__ uint32_t Bs_hi[128 * P];
    __shared__ uint32_t Bs_lo[128 * P];

    const int tid    = threadIdx.x;
    const int i0     = blockIdx.x * 128;
    const int lane   = tid & 31;
    const int wid    = tid >> 5;
    const int warp_m = wid & 3;
    const int warp_n = wid >> 2;
    const int qr     = lane >> 2;   // groupID
    const int qc     = lane & 3;    // thread-in-group

    float acc[2][8][4];
#pragma unroll
    for (int mt = 0; mt < 2; ++mt)
#pragma unroll
        for (int nt = 0; nt < 8; ++nt)
#pragma unroll
            for (int r = 0; r < 4; ++r) acc[mt][nt][r] = 0.f;

    const int  lrow = tid >> 1;          // 0..127
    const int  lkq  = (tid & 1) * 16;    // k offset 0 or 16
    const int  gi   = i0 + lrow;
    const bool ok   = (gi < nrows);

    for (int kc = 0; kc < KDIM; kc += 32) {
        __syncthreads();   // previous-iteration fragment reads done

#pragma unroll
        for (int q = 0; q < 4; ++q) {
            const int gk = kc + lkq + q * 4;
            const int k2 = (lkq + q * 4) >> 1;
            // ---- A ----
            float4 av = make_float4(0.f, 0.f, 0.f, 0.f);
            if (ok) {
                if (MODE == 0)       av = *(const float4*)(A0 + (size_t)gi * 128 + gk);
                else if (gk < 128)   av = *(const float4*)(g_nacc + (size_t)gi * 128 + gk);
                else                 av = *(const float4*)(A0 + (size_t)gi * 128 + (gk - 128));
            }
            uint32_t h0, l0, h1, l1;
            pack2(av.x, av.y, h0, l0);
            pack2(av.z, av.w, h1, l1);
            *(uint2*)(As_hi + lrow * P + k2) = make_uint2(h0, h1);
            *(uint2*)(As_lo + lrow * P + k2) = make_uint2(l0, l1);
            // ---- B (W row lrow always valid) ----
            float4 bv = *(const float4*)(W + (size_t)lrow * KDIM + gk);
            pack2(bv.x, bv.y, h0, l0);
            pack2(bv.z, bv.w, h1, l1);
            *(uint2*)(Bs_hi + lrow * P + k2) = make_uint2(h0, h1);
            *(uint2*)(Bs_lo + lrow * P + k2) = make_uint2(l0, l1);
        }
        __syncthreads();

#pragma unroll
        for (int s = 0; s < 2; ++s) {
            const int ks = s * 8;
            uint32_t ahi[2][4], alo[2][4];
#pragma unroll
            for (int mt = 0; mt < 2; ++mt) {
                const int base = (warp_m * 32 + mt * 16 + qr) * P + ks + qc;
                ahi[mt][0] = As_hi[base];
                ahi[mt][1] = As_hi[base + 8 * P];
                ahi[mt][2] = As_hi[base + 4];
                ahi[mt][3] = As_hi[base + 8 * P + 4];
                alo[mt][0] = As_lo[base];
                alo[mt][1] = As_lo[base + 8 * P];
                alo[mt][2] = As_lo[base + 4];
                alo[mt][3] = As_lo[base + 8 * P + 4];
            }
#pragma unroll
            for (int nt = 0; nt < 8; ++nt) {
                const int bb = (warp_n * 64 + nt * 8 + qr) * P + ks + qc;
                uint32_t bh[2] = { Bs_hi[bb], Bs_hi[bb + 4] };
                uint32_t bl[2] = { Bs_lo[bb], Bs_lo[bb + 4] };
#pragma unroll
                for (int mt = 0; mt < 2; ++mt) {
                    mma_bf16(acc[mt][nt], ahi[mt], bh);
                    mma_bf16(acc[mt][nt], alo[mt], bh);
                    mma_bf16(acc[mt][nt], ahi[mt], bl);
                }
            }
        }
    }

    // ---- Epilogue: bias + relu ----
    float* op = (MODE == 0) ? g_nsrc : out;
#pragma unroll
    for (int mt = 0; mt < 2; ++mt) {
#pragma unroll
        for (int half = 0; half < 2; ++half) {
            const int row = i0 + warp_m * 32 + mt * 16 + qr + half * 8;
            if (row < nrows) {
#pragma unroll
                for (int nt = 0; nt < 8; ++nt) {
                    const int col = warp_n * 64 + nt * 8 + qc * 2;
                    float2 v;
                    v.x = fmaxf(acc[mt][nt][half * 2 + 0] + bias[col],     0.f);
                    v.y = fmaxf(acc[mt][nt][half * 2 + 1] + bias[col + 1], 0.f);
                    *(float2*)(op + (size_t)row * 128 + col) = v;
                }
            }
        }
    }
}

// ---------------------------------------------------------------------------
extern "C" void kernel_launch(void* const* d_in, const int* in_sizes, int n_in,
                              void* d_out, int out_size)
{
    const float* h_src   = (const float*)d_in[0];
    const float* h_dst   = (const float*)d_in[1];
    const float* weights = (const float*)d_in[2];
    const int*   esrc    = (const int*)d_in[3];
    const int*   edst    = (const int*)d_in[4];
    const float* Q_w     = (const float*)d_in[5];
    const float* Q_b     = (const float*)d_in[6];
    const float* W_w     = (const float*)d_in[7];
    const float* W_b     = (const float*)d_in[8];
    float*       out     = (float*)d_out;

    // GEMM1: h_src -> g_nsrc  (independent of CSR build)
    gemm_bf16x3<128, 0><<<(N_SRC + 127) / 128, 256>>>(h_src, Q_w, Q_b, nullptr, N_SRC);

    // CSR build
    zero_cnt_kernel<<<(NSCAN * SCAN_B + 255) / 256, 256>>>();
    hist_kernel<<<(N_EDGES + 255) / 256, 256>>>(edst);
    scan_block_kernel<<<NSCAN, 256>>>();
    scan_top_kernel<<<1, 32>>>();
    scan_down_kernel<<<NSCAN, SCAN_B>>>();
    scatter_kernel<<<(N_EDGES + 255) / 256, 256>>>(esrc, edst, weights);

    // Aggregate (normalized) into g_nacc
    aggregate_csr_kernel<<<(N_DST * 32 + 255) / 256, 256>>>();

    // GEMM2: [g_nacc | h_dst] -> out
    gemm_bf16x3<256, 1><<<(N_DST + 127) / 128, 256>>>(h_dst, W_w, W_b, out, N_DST);
}